// round 1
// baseline (speedup 1.0000x reference)
#include <cuda_runtime.h>

#define FULLMASK 0xFFFFFFFFu

// Sum 8 products of two 8-float (2x float4) vectors.
__device__ __forceinline__ float d8(const float4& a0, const float4& a1,
                                    const float4& b0, const float4& b1) {
    float s = a0.x * b0.x;
    s = fmaf(a0.y, b0.y, s);
    s = fmaf(a0.z, b0.z, s);
    s = fmaf(a0.w, b0.w, s);
    s = fmaf(a1.x, b1.x, s);
    s = fmaf(a1.y, b1.y, s);
    s = fmaf(a1.z, b1.z, s);
    s = fmaf(a1.w, b1.w, s);
    return s;
}

__device__ __forceinline__ float warp_sum(float v) {
#pragma unroll
    for (int o = 16; o; o >>= 1) v += __shfl_xor_sync(FULLMASK, v, o);
    return v;
}

// soft_rank with KL regularization, strength 2.0, n = 4.
// v[4] -> out[4], fully register-resident (constant-index only).
__device__ __forceinline__ void softrank4(const float v[4], float out[4]) {
    float th[4];
    int pi[4];
#pragma unroll
    for (int m = 0; m < 4; m++) { th[m] = v[m] * 0.5f; pi[m] = m; }

    // descending sort network on 4 elems: (0,1)(2,3)(0,2)(1,3)(1,2)
#define CSWAP(a, b)                                     \
    do {                                                \
        if (th[a] < th[b]) {                            \
            float tf = th[a]; th[a] = th[b]; th[b] = tf;\
            int ti = pi[a]; pi[a] = pi[b]; pi[b] = ti;  \
        }                                               \
    } while (0)
    CSWAP(0, 1); CSWAP(2, 3); CSWAP(0, 2); CSWAP(1, 3); CSWAP(1, 2);
#undef CSWAP

    // log of cumulative weight sums, w = [4,3,2,1]
    // cw[i][j] = sum w[i..j]:
    // i=0: 4 7 9 10 ; i=1: 3 5 6 ; i=2: 2 3 ; i=3: 1
    const float lcw00 = 1.3862943611198906f;  // log 4
    const float lcw01 = 1.9459101090932196f;  // log 7
    const float lcw02 = 2.1972245773362196f;  // log 9
    const float lcw03 = 2.302585092994046f;   // log 10
    const float lcw11 = 1.0986122886681098f;  // log 3
    const float lcw12 = 1.6094379124341003f;  // log 5
    const float lcw13 = 1.791759469228055f;   // log 6
    const float lcw22 = 0.6931471805599453f;  // log 2
    const float lcw23 = 1.0986122886681098f;  // log 3
    const float lcw33 = 0.0f;                 // log 1

    // B[i][j] = LSE(th[i..j]) - log(cw[i][j]); th descending so th[i] is seg max.
    float B[4][4];
    {
        float run;
        run = 1.0f;                       B[0][0] = th[0] - lcw00;
        run += __expf(th[1] - th[0]);     B[0][1] = th[0] + __logf(run) - lcw01;
        run += __expf(th[2] - th[0]);     B[0][2] = th[0] + __logf(run) - lcw02;
        run += __expf(th[3] - th[0]);     B[0][3] = th[0] + __logf(run) - lcw03;
        run = 1.0f;                       B[1][1] = th[1] - lcw11;
        run += __expf(th[2] - th[1]);     B[1][2] = th[1] + __logf(run) - lcw12;
        run += __expf(th[3] - th[1]);     B[1][3] = th[1] + __logf(run) - lcw13;
        run = 1.0f;                       B[2][2] = th[2] - lcw22;
        run += __expf(th[3] - th[2]);     B[2][3] = th[2] + __logf(run) - lcw23;
        B[3][3] = th[3] - lcw33;
    }

    // dual[k] = min_{i<=k} max_{j>=k} B[i][j]
    float dual[4];
    {
        // reverse cummax per row: T[i][k] = max_{j>=k} B[i][j]
        float T0_3 = B[0][3], T0_2 = fmaxf(B[0][2], T0_3),
              T0_1 = fmaxf(B[0][1], T0_2), T0_0 = fmaxf(B[0][0], T0_1);
        float T1_3 = B[1][3], T1_2 = fmaxf(B[1][2], T1_3),
              T1_1 = fmaxf(B[1][1], T1_2);
        float T2_3 = B[2][3], T2_2 = fmaxf(B[2][2], T2_3);
        float T3_3 = B[3][3];
        dual[0] = T0_0;
        dual[1] = fminf(T0_1, T1_1);
        dual[2] = fminf(fminf(T0_2, T1_2), T2_2);
        dual[3] = fminf(fminf(T0_3, T1_3), fminf(T2_3, T3_3));
    }

#pragma unroll
    for (int k = 0; k < 4; k++) {
        float r = __expf(th[k] - dual[k]);
        out[0] = (pi[k] == 0) ? r : out[0];
        out[1] = (pi[k] == 1) ? r : out[1];
        out[2] = (pi[k] == 2) ? r : out[2];
        out[3] = (pi[k] == 3) ? r : out[3];
    }
}

__global__ void zero_out_kernel(float* out) { out[0] = 0.0f; }

// One warp per group g = (half, id): 4 query rows (i) x 4 positive rows (j),
// all 3 features. 1024 groups total.
__global__ void __launch_bounds__(128)
cmrr_main_kernel(const float* __restrict__ f0, const float* __restrict__ f1,
                 const float* __restrict__ f2, float* __restrict__ out) {
    const int gw = (blockIdx.x * blockDim.x + threadIdx.x) >> 5;  // 0..1023
    const int lane = threadIdx.x & 31;

    const int half = gw >> 9;
    const int id = gw & 511;
    const int ib = half * 2048 + id * 4;          // query rows   i = ib..ib+3
    const int jb = (1 - half) * 2048 + id * 4;    // positive rows j = jb..jb+3

    float ranks[3][4];  // lane r<4: normalized ranks of row ib+r per feature
#pragma unroll
    for (int t = 0; t < 3; t++) {
        const float* __restrict__ f = (t == 0) ? f0 : ((t == 1) ? f1 : f2);

        // Cooperative load: lane owns elems {lane*4 .. +3} and {(lane+32)*4 .. +3}
        float4 fi[4][2], fj[4][2];
#pragma unroll
        for (int r = 0; r < 4; r++) {
            const float4* pi4 =
                reinterpret_cast<const float4*>(f + (size_t)(ib + r) * 256);
            const float4* pj4 =
                reinterpret_cast<const float4*>(f + (size_t)(jb + r) * 256);
            fi[r][0] = pi4[lane];
            fi[r][1] = pi4[lane + 32];
            fj[r][0] = pj4[lane];
            fj[r][1] = pj4[lane + 32];
        }

        float acc[4][4], sqi[4], sqj[4];
#pragma unroll
        for (int r = 0; r < 4; r++) {
            sqi[r] = d8(fi[r][0], fi[r][1], fi[r][0], fi[r][1]);
            sqj[r] = d8(fj[r][0], fj[r][1], fj[r][0], fj[r][1]);
#pragma unroll
            for (int c = 0; c < 4; c++)
                acc[r][c] = d8(fi[r][0], fi[r][1], fj[c][0], fj[c][1]);
        }
        // butterfly reductions: every lane ends with the full sums
#pragma unroll
        for (int r = 0; r < 4; r++) {
            sqi[r] = warp_sum(sqi[r]);
            sqj[r] = warp_sum(sqj[r]);
#pragma unroll
            for (int c = 0; c < 4; c++) acc[r][c] = warp_sum(acc[r][c]);
        }

        // lane r (0..3) handles row ib+r; lanes >=4 compute row 0 (discarded)
        float sr = (lane == 1) ? sqi[1]
                 : (lane == 2) ? sqi[2]
                 : (lane == 3) ? sqi[3] : sqi[0];
        float v[4];
#pragma unroll
        for (int c = 0; c < 4; c++) {
            float a = (lane == 1) ? acc[1][c]
                    : (lane == 2) ? acc[2][c]
                    : (lane == 3) ? acc[3][c] : acc[0][c];
            float d2 = sr + sqj[c] - 2.0f * a;
            v[c] = sqrtf(fmaxf(d2, 1e-12f));
        }
        softrank4(v, ranks[t]);
    }

    // center + normalize each feature's rank vector (per lane)
#pragma unroll
    for (int t = 0; t < 3; t++) {
        float m =
            0.25f * (ranks[t][0] + ranks[t][1] + ranks[t][2] + ranks[t][3]);
        float n2 = 0.0f;
#pragma unroll
        for (int c = 0; c < 4; c++) {
            ranks[t][c] -= m;
            n2 = fmaf(ranks[t][c], ranks[t][c], n2);
        }
        float inv = rsqrtf(n2);
#pragma unroll
        for (int c = 0; c < 4; c++) ranks[t][c] *= inv;
    }

    // spearman over pairs (0,1),(0,2),(1,2): loss = (sum sp + 3) / 6
    float sp = 0.0f;
#pragma unroll
    for (int c = 0; c < 4; c++) {
        sp = fmaf(ranks[0][c], ranks[1][c], sp);
        sp = fmaf(ranks[0][c], ranks[2][c], sp);
        sp = fmaf(ranks[1][c], ranks[2][c], sp);
    }
    float loss = (sp + 3.0f) * (1.0f / 6.0f);
    if (lane >= 4) loss = 0.0f;

    // sum lanes 0..3, accumulate mean over the 4096 rows
    loss += __shfl_xor_sync(FULLMASK, loss, 1);
    loss += __shfl_xor_sync(FULLMASK, loss, 2);
    if (lane == 0) atomicAdd(out, loss * (1.0f / 4096.0f));
}

extern "C" void kernel_launch(void* const* d_in, const int* in_sizes, int n_in,
                              void* d_out, int out_size) {
    const float* f0 = (const float*)d_in[0];
    const float* f1 = (const float*)d_in[1];
    const float* f2 = (const float*)d_in[2];
    float* out = (float*)d_out;

    zero_out_kernel<<<1, 1>>>(out);
    // 1024 warps = 256 blocks x 4 warps
    cmrr_main_kernel<<<256, 128>>>(f0, f1, f2, out);
}

// round 2
// speedup vs baseline: 1.4588x; 1.4588x over previous
#include <cuda_runtime.h>

#define FULLMASK 0xFFFFFFFFu

// Sum 8 products of two 8-float (2x float4) vectors.
__device__ __forceinline__ float d8(const float4& a0, const float4& a1,
                                    const float4& b0, const float4& b1) {
    float s = a0.x * b0.x;
    s = fmaf(a0.y, b0.y, s);
    s = fmaf(a0.z, b0.z, s);
    s = fmaf(a0.w, b0.w, s);
    s = fmaf(a1.x, b1.x, s);
    s = fmaf(a1.y, b1.y, s);
    s = fmaf(a1.z, b1.z, s);
    s = fmaf(a1.w, b1.w, s);
    return s;
}

__device__ __forceinline__ float warp_sum(float v) {
#pragma unroll
    for (int o = 16; o; o >>= 1) v += __shfl_xor_sync(FULLMASK, v, o);
    return v;
}

// soft_rank with KL regularization, strength 2.0, n = 4.
// v[4] -> out[4], fully register-resident (constant-index only).
__device__ __forceinline__ void softrank4(const float v[4], float out[4]) {
    float th[4];
    int pi[4];
#pragma unroll
    for (int m = 0; m < 4; m++) { th[m] = v[m] * 0.5f; pi[m] = m; }

    // descending sort network on 4 elems: (0,1)(2,3)(0,2)(1,3)(1,2)
#define CSWAP(a, b)                                     \
    do {                                                \
        if (th[a] < th[b]) {                            \
            float tf = th[a]; th[a] = th[b]; th[b] = tf;\
            int ti = pi[a]; pi[a] = pi[b]; pi[b] = ti;  \
        }                                               \
    } while (0)
    CSWAP(0, 1); CSWAP(2, 3); CSWAP(0, 2); CSWAP(1, 3); CSWAP(1, 2);
#undef CSWAP

    // log of cumulative weight sums, w = [4,3,2,1]
    const float lcw00 = 1.3862943611198906f;  // log 4
    const float lcw01 = 1.9459101090932196f;  // log 7
    const float lcw02 = 2.1972245773362196f;  // log 9
    const float lcw03 = 2.302585092994046f;   // log 10
    const float lcw11 = 1.0986122886681098f;  // log 3
    const float lcw12 = 1.6094379124341003f;  // log 5
    const float lcw13 = 1.791759469228055f;   // log 6
    const float lcw22 = 0.6931471805599453f;  // log 2
    const float lcw23 = 1.0986122886681098f;  // log 3
    const float lcw33 = 0.0f;                 // log 1

    // B[i][j] = LSE(th[i..j]) - log(cw[i][j]); th descending so th[i] is seg max.
    float B[4][4];
    {
        float run;
        run = 1.0f;                       B[0][0] = th[0] - lcw00;
        run += __expf(th[1] - th[0]);     B[0][1] = th[0] + __logf(run) - lcw01;
        run += __expf(th[2] - th[0]);     B[0][2] = th[0] + __logf(run) - lcw02;
        run += __expf(th[3] - th[0]);     B[0][3] = th[0] + __logf(run) - lcw03;
        run = 1.0f;                       B[1][1] = th[1] - lcw11;
        run += __expf(th[2] - th[1]);     B[1][2] = th[1] + __logf(run) - lcw12;
        run += __expf(th[3] - th[1]);     B[1][3] = th[1] + __logf(run) - lcw13;
        run = 1.0f;                       B[2][2] = th[2] - lcw22;
        run += __expf(th[3] - th[2]);     B[2][3] = th[2] + __logf(run) - lcw23;
        B[3][3] = th[3] - lcw33;
    }

    // dual[k] = min_{i<=k} max_{j>=k} B[i][j]
    float dual[4];
    {
        float T0_3 = B[0][3], T0_2 = fmaxf(B[0][2], T0_3),
              T0_1 = fmaxf(B[0][1], T0_2), T0_0 = fmaxf(B[0][0], T0_1);
        float T1_3 = B[1][3], T1_2 = fmaxf(B[1][2], T1_3),
              T1_1 = fmaxf(B[1][1], T1_2);
        float T2_3 = B[2][3], T2_2 = fmaxf(B[2][2], T2_3);
        float T3_3 = B[3][3];
        dual[0] = T0_0;
        dual[1] = fminf(T0_1, T1_1);
        dual[2] = fminf(fminf(T0_2, T1_2), T2_2);
        dual[3] = fminf(fminf(T0_3, T1_3), fminf(T2_3, T3_3));
    }

#pragma unroll
    for (int k = 0; k < 4; k++) {
        float r = __expf(th[k] - dual[k]);
        out[0] = (pi[k] == 0) ? r : out[0];
        out[1] = (pi[k] == 1) ? r : out[1];
        out[2] = (pi[k] == 2) ? r : out[2];
        out[3] = (pi[k] == 3) ? r : out[3];
    }
}

__global__ void zero_out_kernel(float* out) { out[0] = 0.0f; }

// One block per id (512 blocks), 3 warps = one per feature.
// Each warp computes the 4x4 distance matrix between rows {id*4..+3} (half 0)
// and rows {2048+id*4..+3} (half 1). Rows of D give the soft-rank inputs for
// the half-0 queries; columns of D (= rows of D^T) give them for the half-1
// queries. Every feature row is loaded from GMEM exactly once.
__global__ void __launch_bounds__(96)
cmrr_main_kernel(const float* __restrict__ f0, const float* __restrict__ f1,
                 const float* __restrict__ f2, float* __restrict__ out) {
    __shared__ float4 sh[3][8];  // [feature][row-slot] -> normalized ranks

    const int id = blockIdx.x;            // 0..511
    const int t = threadIdx.x >> 5;       // feature 0..2
    const int lane = threadIdx.x & 31;

    const int ib = id * 4;                // half-0 rows
    const int jb = 2048 + id * 4;         // half-1 rows

    const float* __restrict__ f = (t == 0) ? f0 : ((t == 1) ? f1 : f2);

    // Cooperative load: lane owns elems {lane*4..+3} and {(lane+32)*4..+3}
    float4 fa[4][2], fb[4][2];
#pragma unroll
    for (int r = 0; r < 4; r++) {
        const float4* pa =
            reinterpret_cast<const float4*>(f + (size_t)(ib + r) * 256);
        const float4* pb =
            reinterpret_cast<const float4*>(f + (size_t)(jb + r) * 256);
        fa[r][0] = pa[lane];
        fa[r][1] = pa[lane + 32];
        fb[r][0] = pb[lane];
        fb[r][1] = pb[lane + 32];
    }

    float acc[4][4], sqa[4], sqb[4];
#pragma unroll
    for (int r = 0; r < 4; r++) {
        sqa[r] = d8(fa[r][0], fa[r][1], fa[r][0], fa[r][1]);
        sqb[r] = d8(fb[r][0], fb[r][1], fb[r][0], fb[r][1]);
#pragma unroll
        for (int c = 0; c < 4; c++)
            acc[r][c] = d8(fa[r][0], fa[r][1], fb[c][0], fb[c][1]);
    }
    // butterfly reductions: every lane ends with the full sums
#pragma unroll
    for (int r = 0; r < 4; r++) {
        sqa[r] = warp_sum(sqa[r]);
        sqb[r] = warp_sum(sqb[r]);
#pragma unroll
        for (int c = 0; c < 4; c++) acc[r][c] = warp_sum(acc[r][c]);
    }

    // d[r][c] = dist(row ib+r, row jb+c)
    float d[4][4];
#pragma unroll
    for (int r = 0; r < 4; r++)
#pragma unroll
        for (int c = 0; c < 4; c++) {
            float d2 = sqa[r] + sqb[c] - 2.0f * acc[r][c];
            d[r][c] = sqrtf(fmaxf(d2, 1e-12f));
        }

    // lanes 0..3: query row ib+l   -> v[c] = d[l][c]
    // lanes 4..7: query row jb+(l-4) -> v[c] = d[c][l-4]
    const int rr = lane & 3;
    const bool trans = (lane & 4) != 0;
    float v[4];
#pragma unroll
    for (int c = 0; c < 4; c++) {
        float drc = (rr == 1) ? d[1][c]
                  : (rr == 2) ? d[2][c]
                  : (rr == 3) ? d[3][c] : d[0][c];
        float dcr = (rr == 1) ? d[c][1]
                  : (rr == 2) ? d[c][2]
                  : (rr == 3) ? d[c][3] : d[c][0];
        v[c] = trans ? dcr : drc;
    }

    float rk[4];
    softrank4(v, rk);

    // center + normalize
    {
        float m = 0.25f * (rk[0] + rk[1] + rk[2] + rk[3]);
        float n2 = 0.0f;
#pragma unroll
        for (int c = 0; c < 4; c++) {
            rk[c] -= m;
            n2 = fmaf(rk[c], rk[c], n2);
        }
        float inv = rsqrtf(n2);
#pragma unroll
        for (int c = 0; c < 4; c++) rk[c] *= inv;
    }

    if (lane < 8) sh[t][lane] = make_float4(rk[0], rk[1], rk[2], rk[3]);
    __syncthreads();

    // warp 0: spearman across feature pairs for the 8 query rows, reduce,
    // accumulate the global mean.
    if (t == 0) {
        float loss = 0.0f;
        if (lane < 8) {
            float4 r0 = sh[0][lane];
            float4 r1 = sh[1][lane];
            float4 r2 = sh[2][lane];
            float sp = r0.x * r1.x + r0.y * r1.y + r0.z * r1.z + r0.w * r1.w;
            sp += r0.x * r2.x + r0.y * r2.y + r0.z * r2.z + r0.w * r2.w;
            sp += r1.x * r2.x + r1.y * r2.y + r1.z * r2.z + r1.w * r2.w;
            loss = (sp + 3.0f) * (1.0f / 6.0f);
        }
        loss += __shfl_xor_sync(FULLMASK, loss, 1);
        loss += __shfl_xor_sync(FULLMASK, loss, 2);
        loss += __shfl_xor_sync(FULLMASK, loss, 4);
        if (lane == 0) atomicAdd(out, loss * (1.0f / 4096.0f));
    }
}

extern "C" void kernel_launch(void* const* d_in, const int* in_sizes, int n_in,
                              void* d_out, int out_size) {
    const float* f0 = (const float*)d_in[0];
    const float* f1 = (const float*)d_in[1];
    const float* f2 = (const float*)d_in[2];
    float* out = (float*)d_out;

    zero_out_kernel<<<1, 1>>>(out);
    cmrr_main_kernel<<<512, 96>>>(f0, f1, f2, out);
}